// round 1
// baseline (speedup 1.0000x reference)
#include <cuda_runtime.h>

// SparseSpikingConv2D: 3x3 SAME conv (N=32,Cin=64,Cout=128,64x64) + LIF membrane
// + multi-threshold spike. fp32 direct conv using Blackwell packed fma.rn.f32x2.

#define NB   32
#define CIN  64
#define COUT 128
#define HDIM 64
#define WDIM 64
#define EPSV 1e-8f

__device__ float g_inv_norm[COUT];

// Per-Cout kernel squared-norm reciprocal: norm[co] = sum_{kk,ci} kernel[kk,ci,co]^2
__global__ void prep_kernel(const float* __restrict__ kern) {
    int co = threadIdx.x;  // 128 threads
    float s = 0.f;
#pragma unroll 4
    for (int i = 0; i < 9 * CIN; i++) {
        float v = kern[i * COUT + co];
        s += v * v;
    }
    g_inv_norm[co] = 1.f / (s + EPSV);
}

__device__ __forceinline__ unsigned long long dup2(float f) {
    unsigned long long r;
    asm("mov.b64 %0,{%1,%1};" : "=l"(r) : "f"(f));
    return r;
}
__device__ __forceinline__ void ffma2(unsigned long long& d, unsigned long long a,
                                      unsigned long long b) {
    asm("fma.rn.f32x2 %0,%1,%2,%0;" : "+l"(d) : "l"(a), "l"(b));
}

// Block: one (n, h0..h0+1) slab, all 128 Cout x 64 W.
// 256 threads: thread tile = 8 Cout (4 f32x2 pairs) x 4 W x 2 H.
__global__ __launch_bounds__(256, 2)
void conv_spike_kernel(const float* __restrict__ x, const float* __restrict__ mem,
                       const float* __restrict__ kern, const float* __restrict__ beta_p,
                       const float* __restrict__ b_p, float* __restrict__ out) {
    __shared__ float sW[8 * 9 * 128];   // [cj][kidx][co]
    __shared__ float sX[8 * 4 * 72];    // [cj][row(4)][col 0..65 (input col-1..64)]
    __shared__ float snorm[COUT];
    __shared__ float sb[COUT];

    const int tid = threadIdx.x;
    const int bid = blockIdx.x;
    const int n  = bid >> 5;          // 32 blocks per n
    const int h0 = (bid & 31) << 1;   // 2 rows per block
    const int wg = tid & 15;
    const int cg = tid >> 4;
    const int wb  = wg << 2;          // w base (4 wide)
    const int cob = cg << 3;          // cout base (8 wide)

    if (tid < COUT) {
        snorm[tid] = g_inv_norm[tid];
        sb[tid]    = b_p[tid];
    }

    unsigned long long acc[4][2][4];  // [co-pair][hh][ww], f32x2 each
#pragma unroll
    for (int p = 0; p < 4; p++)
#pragma unroll
        for (int h = 0; h < 2; h++)
#pragma unroll
            for (int w = 0; w < 4; w++) acc[p][h][w] = 0ull;

#pragma unroll 1
    for (int c0 = 0; c0 < CIN; c0 += 8) {
        __syncthreads();
        // stage weights for 8 input channels: sW[cj][kidx][co]
#pragma unroll 1
        for (int i = tid; i < 8 * 9 * 128; i += 256) {
            int cj  = i / 1152;
            int rem = i - cj * 1152;
            int kidx = rem >> 7;
            int co   = rem & 127;
            sW[i] = kern[kidx * (CIN * COUT) + (c0 + cj) * COUT + co];
        }
        // stage x: 4 input rows (h0-1..h0+2) with 1-col halo each side
#pragma unroll 1
        for (int i = tid; i < 8 * 4 * 66; i += 256) {
            int cj  = i / 264;
            int rem = i - cj * 264;
            int r = rem / 66;
            int c = rem - r * 66;
            int gr = h0 - 1 + r;
            int gw = c - 1;
            float v = 0.f;
            if (gr >= 0 && gr < HDIM && gw >= 0 && gw < WDIM)
                v = x[((n * CIN + c0 + cj) * HDIM + gr) * WDIM + gw];
            sX[cj * 288 + r * 72 + c] = v;
        }
        __syncthreads();

#pragma unroll 1
        for (int cj = 0; cj < 8; cj++) {
            const float* xr    = &sX[cj * 288 + wb];
            const float* wbase = &sW[cj * 1152 + cob];
#pragma unroll
            for (int kh = 0; kh < 3; kh++) {
                unsigned long long xx0[6], xx1[6];
#pragma unroll
                for (int j = 0; j < 6; j++) {
                    xx0[j] = dup2(xr[kh * 72 + j]);        // row for hh=0
                    xx1[j] = dup2(xr[(kh + 1) * 72 + j]);  // row for hh=1
                }
#pragma unroll
                for (int kw = 0; kw < 3; kw++) {
                    const ulonglong2* wp =
                        (const ulonglong2*)(wbase + (kh * 3 + kw) * 128);
                    ulonglong2 wA = wp[0];  // co pairs (0,1),(2,3)
                    ulonglong2 wB = wp[1];  // co pairs (4,5),(6,7)
#pragma unroll
                    for (int w = 0; w < 4; w++) {
                        unsigned long long a0 = xx0[w + kw];
                        unsigned long long a1 = xx1[w + kw];
                        ffma2(acc[0][0][w], wA.x, a0);
                        ffma2(acc[1][0][w], wA.y, a0);
                        ffma2(acc[2][0][w], wB.x, a0);
                        ffma2(acc[3][0][w], wB.y, a0);
                        ffma2(acc[0][1][w], wA.x, a1);
                        ffma2(acc[1][1][w], wA.y, a1);
                        ffma2(acc[2][1][w], wB.x, a1);
                        ffma2(acc[3][1][w], wB.y, a1);
                    }
                }
            }
        }
    }

    // Fused epilogue: LIF membrane + multi-threshold spike, write spk then final_mem.
    const float beta = *beta_p;
    const float omb  = 1.f - beta;
    const int FM_OFF = NB * COUT * HDIM * WDIM;  // 16777216

#pragma unroll
    for (int k = 0; k < 8; k++) {
        const int co = cob + k;
        const float invn = snorm[co];
        const float bb   = sb[co];
#pragma unroll
        for (int hh = 0; hh < 2; hh++) {
            const int base = ((n * COUT + co) * HDIM + h0 + hh) * WDIM + wb;
            float4 m4 = *(const float4*)(mem + base);
            float mv[4] = {m4.x, m4.y, m4.z, m4.w};
            float sv[4], fv[4];
#pragma unroll
            for (int w = 0; w < 4; w++) {
                float2 pr = *(float2*)&acc[k >> 1][hh][w];
                float cv = (k & 1) ? pr.y : pr.x;
                float nm = mv[w] * beta + cv * omb;
                float mt = nm * invn - bb;
                float cnt = (float)((mt > 0.f) + (mt > 1.f) + (mt > 2.f) + (mt > 3.f));
                sv[w] = cnt;
                fv[w] = (cnt > 0.f) ? 0.f : nm;
            }
            *(float4*)(out + base)          = make_float4(sv[0], sv[1], sv[2], sv[3]);
            *(float4*)(out + FM_OFF + base) = make_float4(fv[0], fv[1], fv[2], fv[3]);
        }
    }
}

extern "C" void kernel_launch(void* const* d_in, const int* in_sizes, int n_in,
                              void* d_out, int out_size) {
    const float* x    = (const float*)d_in[0];
    const float* mem  = (const float*)d_in[1];
    const float* kern = (const float*)d_in[2];
    const float* beta = (const float*)d_in[3];
    const float* b    = (const float*)d_in[4];
    float* out = (float*)d_out;

    prep_kernel<<<1, COUT>>>(kern);
    conv_spike_kernel<<<NB * (HDIM / 2), 256>>>(x, mem, kern, beta, b, out);
}

// round 3
// speedup vs baseline: 1.7147x; 1.7147x over previous
#include <cuda_runtime.h>
#include <cstdint>

#define NB   32
#define CIN  64
#define COUT 128
#define HDIM 64
#define WDIM 64
#define EPSV 1e-8f
#define FM_OFF (NB * COUT * HDIM * WDIM)

// dynamic smem layout (floats):
//   sW: [0, 18432)          2 buffers x 9216  ([cj 8][kidx 9][co 128])
//   sX: [18432, 23040)      2 buffers x 2304  ([cj 8][r 4][72] ; 66 valid cols)
//   snorm: [23040, 23168)
//   sb:    [23168, 23296)
#define SM_SW   0
#define SM_SX   18432
#define SM_NORM 23040
#define SM_B    23168
#define SMEM_BYTES (23296 * 4)

__device__ float g_inv_norm[COUT];

// ---------- prep: per-Cout 1/(||k||^2 + eps), 4-way split reduction ----------
__global__ void prep_norm(const float* __restrict__ kern) {
    __shared__ float red[512];
    int t = threadIdx.x;            // 512 threads
    int co = t & 127;
    int part = t >> 7;              // 0..3, 144 terms each
    float s = 0.f;
#pragma unroll 4
    for (int i = part * 144; i < part * 144 + 144; i++) {
        float v = kern[i * COUT + co];
        s += v * v;
    }
    red[t] = s;
    __syncthreads();
    if (t < 128)
        g_inv_norm[co] = 1.f / (red[co] + red[co + 128] + red[co + 256] + red[co + 384] + EPSV);
}

// ---------- helpers ----------
__device__ __forceinline__ unsigned long long dup2(float f) {
    unsigned long long r;
    asm("mov.b64 %0,{%1,%1};" : "=l"(r) : "f"(f));
    return r;
}
__device__ __forceinline__ void ffma2(unsigned long long& d, unsigned long long a,
                                      unsigned long long b) {
    asm("fma.rn.f32x2 %0,%1,%2,%0;" : "+l"(d) : "l"(a), "l"(b));
}
__device__ __forceinline__ void cpa16(uint32_t dst, const void* src) {
    asm volatile("cp.async.ca.shared.global [%0], [%1], 16;" :: "r"(dst), "l"(src));
}
__device__ __forceinline__ void cpa4z(uint32_t dst, const void* src, int srcsz) {
    asm volatile("cp.async.ca.shared.global [%0], [%1], 4, %2;"
                 :: "r"(dst), "l"(src), "r"(srcsz));
}
__device__ __forceinline__ void cpcommit() {
    asm volatile("cp.async.commit_group;" ::: "memory");
}
template <int N>
__device__ __forceinline__ void cpwait() {
    asm volatile("cp.async.wait_group %0;" :: "n"(N) : "memory");
}

// load one x row (6 floats at xr) and duplicate each into f32x2
#define LOADROW(dst, xr)                                   \
    {                                                      \
        float4 q = *(const float4*)(xr);                   \
        float2 s = *(const float2*)((xr) + 4);             \
        dst[0] = dup2(q.x); dst[1] = dup2(q.y);            \
        dst[2] = dup2(q.z); dst[3] = dup2(q.w);            \
        dst[4] = dup2(s.x); dst[5] = dup2(s.y);            \
    }

// one kh slab: 3 kw x 4 w x (2 rows) x 4 co-pairs = 24 FFMA2 x ... (96 FFMA2)
#define KHBLOCK(top, bot, Wp, kh)                                         \
    {                                                                     \
        _Pragma("unroll")                                                 \
        for (int kw = 0; kw < 3; kw++) {                                  \
            const ulonglong2* wp = (const ulonglong2*)((Wp) + ((kh)*3 + kw) * 128); \
            ulonglong2 wA = wp[0];                                        \
            ulonglong2 wB = wp[1];                                        \
            _Pragma("unroll")                                             \
            for (int w = 0; w < 4; w++) {                                 \
                unsigned long long a0 = top[w + kw];                      \
                unsigned long long a1 = bot[w + kw];                      \
                ffma2(acc[0][0][w], wA.x, a0);                            \
                ffma2(acc[1][0][w], wA.y, a0);                            \
                ffma2(acc[2][0][w], wB.x, a0);                            \
                ffma2(acc[3][0][w], wB.y, a0);                            \
                ffma2(acc[0][1][w], wA.x, a1);                            \
                ffma2(acc[1][1][w], wA.y, a1);                            \
                ffma2(acc[2][1][w], wB.x, a1);                            \
                ffma2(acc[3][1][w], wB.y, a1);                            \
            }                                                             \
        }                                                                 \
    }

__global__ __launch_bounds__(256, 2)
void conv_spike_kernel(const float* __restrict__ x, const float* __restrict__ mem,
                       const float* __restrict__ kern, const float* __restrict__ beta_p,
                       const float* __restrict__ b_p, float* __restrict__ out) {
    extern __shared__ float sm[];
    const uint32_t smu = (uint32_t)__cvta_generic_to_shared(sm);

    const int tid = threadIdx.x;
    const int bid = blockIdx.x;
    const int n  = bid >> 5;
    const int h0 = (bid & 31) << 1;
    const int wg = tid & 15;
    const int cg = tid >> 4;
    const int wb  = wg << 2;
    const int cob = cg << 3;

    if (tid < COUT) {
        sm[SM_NORM + tid] = g_inv_norm[tid];
        sm[SM_B + tid]    = b_p[tid];
    }

    unsigned long long acc[4][2][4];
#pragma unroll
    for (int p = 0; p < 4; p++)
#pragma unroll
        for (int h = 0; h < 2; h++)
#pragma unroll
            for (int w = 0; w < 4; w++) acc[p][h][w] = 0ull;

    // ---- staging lambda-equivalent: stage cin-block b into buffer buf ----
    // weights: 2304 float4; x: 2112 scalars with zero-filled halo
#define STAGE(bb, buf)                                                            \
    {                                                                             \
        const int c0 = (bb) << 3;                                                 \
        uint32_t wdst = smu + (SM_SW + (buf)*9216) * 4;                           \
        _Pragma("unroll 1")                                                       \
        for (int f = tid; f < 2304; f += 256) {                                   \
            int cj = f / 288;                                                     \
            int rem = f - cj * 288;                                               \
            int kidx = rem >> 5;                                                  \
            int co4 = rem & 31;                                                   \
            cpa16(wdst + f * 16,                                                  \
                  kern + kidx * (CIN * COUT) + (c0 + cj) * COUT + co4 * 4);       \
        }                                                                         \
        uint32_t xdst = smu + (SM_SX + (buf)*2304) * 4;                           \
        _Pragma("unroll 1")                                                       \
        for (int i = tid; i < 2112; i += 256) {                                   \
            int cj = i / 264;                                                     \
            int rem = i - cj * 264;                                               \
            int r = rem / 66;                                                     \
            int c = rem - r * 66;                                                 \
            int gr = h0 - 1 + r;                                                  \
            int gw = c - 1;                                                       \
            bool ok = (gr >= 0) & (gr < HDIM) & (gw >= 0) & (gw < WDIM);          \
            const float* src =                                                    \
                x + (((n * CIN + c0 + cj) * HDIM + (ok ? gr : 0)) * WDIM +        \
                     (ok ? gw : 0));                                              \
            cpa4z(xdst + (cj * 288 + r * 72 + c) * 4, src, ok ? 4 : 0);           \
        }                                                                         \
    }

    STAGE(0, 0);
    cpcommit();

#pragma unroll 1
    for (int b = 0; b < 8; b++) {
        const int buf = b & 1;
        if (b < 7) {
            STAGE(b + 1, buf ^ 1);
            cpcommit();
            cpwait<1>();
        } else {
            cpcommit();
            cpwait<0>();
        }
        __syncthreads();

        const float* sWb = sm + SM_SW + buf * 9216;
        const float* sXb = sm + SM_SX + buf * 2304;

#pragma unroll 1
        for (int cj = 0; cj < 8; cj++) {
            const float* Wp = sWb + cj * 1152 + cob;
            const float* xr = sXb + cj * 288 + wb;

            unsigned long long pa[6], pb[6], pc[6];
            LOADROW(pa, xr);             // row 0
            LOADROW(pb, xr + 72);        // row 1
            LOADROW(pc, xr + 144);       // row 2
            KHBLOCK(pa, pb, Wp, 0);
            LOADROW(pa, xr + 216);       // row 3 (r0 dead)
            KHBLOCK(pb, pc, Wp, 1);
            KHBLOCK(pc, pa, Wp, 2);
        }
        __syncthreads();
    }

    // ---- fused epilogue: LIF membrane + multi-threshold spike ----
    const float beta = *beta_p;
    const float omb  = 1.f - beta;

#pragma unroll
    for (int k = 0; k < 8; k++) {
        const int co = cob + k;
        const float invn = sm[SM_NORM + co];
        const float bb   = sm[SM_B + co];
#pragma unroll
        for (int hh = 0; hh < 2; hh++) {
            const int base = ((n * COUT + co) * HDIM + h0 + hh) * WDIM + wb;
            float4 m4 = *(const float4*)(mem + base);
            float mv[4] = {m4.x, m4.y, m4.z, m4.w};
            float sv[4], fv[4];
#pragma unroll
            for (int w = 0; w < 4; w++) {
                float2 pr = *(float2*)&acc[k >> 1][hh][w];
                float cv = (k & 1) ? pr.y : pr.x;
                float nm = mv[w] * beta + cv * omb;
                float mt = nm * invn - bb;
                float cnt = (float)((mt > 0.f) + (mt > 1.f) + (mt > 2.f) + (mt > 3.f));
                sv[w] = cnt;
                fv[w] = (cnt > 0.f) ? 0.f : nm;
            }
            *(float4*)(out + base)          = make_float4(sv[0], sv[1], sv[2], sv[3]);
            *(float4*)(out + FM_OFF + base) = make_float4(fv[0], fv[1], fv[2], fv[3]);
        }
    }
}

extern "C" void kernel_launch(void* const* d_in, const int* in_sizes, int n_in,
                              void* d_out, int out_size) {
    const float* x    = (const float*)d_in[0];
    const float* mem  = (const float*)d_in[1];
    const float* kern = (const float*)d_in[2];
    const float* beta = (const float*)d_in[3];
    const float* b    = (const float*)d_in[4];
    float* out = (float*)d_out;

    cudaFuncSetAttribute(conv_spike_kernel,
                         cudaFuncAttributeMaxDynamicSharedMemorySize, SMEM_BYTES);

    prep_norm<<<1, 512>>>(kern);
    conv_spike_kernel<<<NB * (HDIM / 2), 256, SMEM_BYTES>>>(x, mem, kern, beta, b, out);
}